// round 3
// baseline (speedup 1.0000x reference)
#include <cuda_runtime.h>
#include <cuda_bf16.h>
#include <cstdint>

// SoftPool_2d: x (32,128,128,64) f32, 2x2/stride-2 windows.
// Per window: h = tanh(win[4x64] @ We[64x128] + be), logit = sigmoid(h @ Wr + br),
// w = softmax(logit over 4), out[64] = sum_w w_i * win_i.
// One thread per window. We^T in shared (broadcast reads). Packed f32x2 FMA.

#define B_  32
#define R_  128
#define C_  128
#define D_  64
#define H_  128

__device__ __forceinline__ unsigned long long pk2(float lo, float hi) {
    unsigned long long r;
    asm("mov.b64 %0, {%1, %2};" : "=l"(r) : "f"(lo), "f"(hi));
    return r;
}
__device__ __forceinline__ void upk2(unsigned long long a, float& lo, float& hi) {
    asm("mov.b64 {%0, %1}, %2;" : "=f"(lo), "=f"(hi) : "l"(a));
}
__device__ __forceinline__ void ffma2(unsigned long long& acc,
                                      unsigned long long a, unsigned long long b) {
    asm("fma.rn.f32x2 %0, %1, %2, %3;" : "=l"(acc) : "l"(a), "l"(b), "l"(acc));
}
__device__ __forceinline__ float tanh_fast(float x) {
    float y;
    asm("tanh.approx.f32 %0, %1;" : "=f"(y) : "f"(x));
    return y;
}

__global__ __launch_bounds__(256, 1)
void softpool2d_kernel(const float* __restrict__ x,
                       const float* __restrict__ We,
                       const float* __restrict__ be,
                       const float* __restrict__ Wr,
                       const float* __restrict__ br,
                       float* __restrict__ out)
{
    __shared__ float sW[H_ * D_];   // transposed: sW[j*64 + d] = We[d*128 + j]
    __shared__ float sB[H_];
    __shared__ float sR[H_];

    const int tid = threadIdx.x;

    // Load + transpose We into shared; biases and restore weights too.
    for (int idx = tid; idx < D_ * H_; idx += 256) {
        int d = idx >> 7;        // / 128
        int j = idx & 127;
        sW[j * D_ + d] = We[idx];
    }
    if (tid < H_) {
        sB[tid] = be[tid];
        sR[tid] = Wr[tid];
    }
    __syncthreads();

    const float brv = br[0];

    const int gidx = blockIdx.x * 256 + tid;       // window id: b*4096 + q*64 + p
    const int b = gidx >> 12;
    const int rem = gidx & 4095;
    const int q = rem >> 6;
    const int p = rem & 63;

    // Base of the 2x2 window: rows 2q,2q+1; cols 2p,2p+1. Row stride C_*D_ floats,
    // col stride D_ floats. All window rows are 256B-aligned (multiples of 64 f32).
    const float* __restrict__ base =
        x + ((size_t)((b * R_ + 2 * q) * C_ + 2 * p)) * D_;
    const float* __restrict__ wptr[4] = {
        base,
        base + D_,
        base + (size_t)C_ * D_,
        base + (size_t)C_ * D_ + D_
    };

    const ulonglong2* __restrict__ sW2 = reinterpret_cast<const ulonglong2*>(sW);

    unsigned long long num[32];                    // 64 fp32 accumulators, packed
#pragma unroll
    for (int k = 0; k < 32; ++k) num[k] = 0ULL;
    float den = 0.0f;

#pragma unroll
    for (int w = 0; w < 4; ++w) {
        const ulonglong2* __restrict__ xp =
            reinterpret_cast<const ulonglong2*>(wptr[w]);

        ulonglong2 v[16];                          // 64 fp32 window values, packed
#pragma unroll
        for (int k = 0; k < 16; ++k) v[k] = xp[k];

        float lsum = 0.0f;
#pragma unroll 2
        for (int j = 0; j < H_; ++j) {
            unsigned long long ax0 = 0ULL, ax1 = 0ULL, ay0 = 0ULL, ay1 = 0ULL;
#pragma unroll
            for (int k = 0; k < 16; ++k) {
                ulonglong2 wv = sW2[j * 16 + k];   // broadcast, conflict-free
                ffma2(((k & 1) ? ax1 : ax0), v[k].x, wv.x);
                ffma2(((k & 1) ? ay1 : ay0), v[k].y, wv.y);
            }
            float f0, f1, f2, f3, f4, f5, f6, f7;
            upk2(ax0, f0, f1);
            upk2(ax1, f2, f3);
            upk2(ay0, f4, f5);
            upk2(ay1, f6, f7);
            float t = ((f0 + f2) + (f1 + f3)) + ((f4 + f6) + (f5 + f7)) + sB[j];
            float h = tanh_fast(t);
            lsum = fmaf(h, sR[j], lsum);
        }

        // logit = sigmoid(lsum + br); unnormalized softmax weight e = exp(logit)
        const float lg = 1.0f / (1.0f + __expf(-(lsum + brv)));
        const float e  = __expf(lg);               // in (1, e): no overflow risk
        den += e;
        const unsigned long long ee = pk2(e, e);
#pragma unroll
        for (int k = 0; k < 16; ++k) {
            ffma2(num[2 * k],     v[k].x, ee);
            ffma2(num[2 * k + 1], v[k].y, ee);
        }
    }

    const float inv = 1.0f / den;
    float4* __restrict__ op = reinterpret_cast<float4*>(out + (size_t)gidx * D_);
#pragma unroll
    for (int k = 0; k < 16; ++k) {
        float a, bv, c, d;
        upk2(num[2 * k],     a, bv);
        upk2(num[2 * k + 1], c, d);
        op[k] = make_float4(a * inv, bv * inv, c * inv, d * inv);
    }
}

extern "C" void kernel_launch(void* const* d_in, const int* in_sizes, int n_in,
                              void* d_out, int out_size)
{
    const float* x  = (const float*)d_in[0];
    const float* We = (const float*)d_in[1];
    const float* be = (const float*)d_in[2];
    const float* Wr = (const float*)d_in[3];
    const float* br = (const float*)d_in[4];
    float* out = (float*)d_out;

    // 32*64*64 = 131072 windows; 256 threads/block -> 512 blocks
    softpool2d_kernel<<<512, 256>>>(x, We, be, Wr, br, out);
}

// round 5
// speedup vs baseline: 1.7912x; 1.7912x over previous
#include <cuda_runtime.h>
#include <cuda_bf16.h>
#include <cstdint>

// SoftPool_2d: x (32,128,128,64) f32, 2x2/stride-2 windows.
// Round 4: j-outer loop with 2 window-positions resident per pass, and
// weights compressed to bf16 in shared (8 weights per LDS.128, unpack via
// shift/mask on the alu pipe). Cuts LDS instruction count 4x vs round 3
// (the measured bottleneck: L1=79.9%).

#define B_  32
#define R_  128
#define C_  128
#define D_  64
#define H_  128

__device__ __forceinline__ unsigned long long pk2(float lo, float hi) {
    unsigned long long r;
    asm("mov.b64 %0, {%1, %2};" : "=l"(r) : "f"(lo), "f"(hi));
    return r;
}
__device__ __forceinline__ void upk2(unsigned long long a, float& lo, float& hi) {
    asm("mov.b64 {%0, %1}, %2;" : "=f"(lo), "=f"(hi) : "l"(a));
}
__device__ __forceinline__ void ffma2(unsigned long long& acc,
                                      unsigned long long a, unsigned long long b) {
    asm("fma.rn.f32x2 %0, %1, %2, %3;" : "=l"(acc) : "l"(a), "l"(b), "l"(acc));
}
// Two packed bf16 (lo16, hi16) -> packed f32x2 (bf16 -> f32 is a <<16).
__device__ __forceinline__ unsigned long long bf2f2(unsigned int u) {
    unsigned int lo = u << 16;
    unsigned int hi = u & 0xFFFF0000u;
    unsigned long long r;
    asm("mov.b64 %0, {%1, %2};" : "=l"(r) : "r"(lo), "r"(hi));
    return r;
}
__device__ __forceinline__ float tanh_fast(float x) {
    float y;
    asm("tanh.approx.f32 %0, %1;" : "=f"(y) : "f"(x));
    return y;
}

__global__ __launch_bounds__(256, 1)
void softpool2d_kernel(const float* __restrict__ x,
                       const float* __restrict__ We,
                       const float* __restrict__ be,
                       const float* __restrict__ Wr,
                       const float* __restrict__ br,
                       float* __restrict__ out)
{
    // Transposed bf16 weights: sW[j*64 + d] = bf16(We[d*128 + j]).
    // Row j = 64 bf16 = 128 bytes = 8 x LDS.128 (broadcast).
    __shared__ __align__(16) __nv_bfloat16 sW[H_ * D_];
    __shared__ float sB[H_];
    __shared__ float sR[H_];

    const int tid = threadIdx.x;

    for (int idx = tid; idx < D_ * H_; idx += 256) {
        int d = idx >> 7;        // / 128
        int j = idx & 127;
        sW[j * D_ + d] = __float2bfloat16(We[idx]);
    }
    if (tid < H_) {
        sB[tid] = be[tid];
        sR[tid] = Wr[tid];
    }
    __syncthreads();

    const float brv = br[0];

    const int gidx = blockIdx.x * 256 + tid;       // window id: b*4096 + q*64 + p
    const int b = gidx >> 12;
    const int rem = gidx & 4095;
    const int q = rem >> 6;
    const int p = rem & 63;

    // Window base: rows 2q,2q+1; cols 2p,2p+1. Positions per pass share a row
    // (512B contiguous). Pass 0: (r,c),(r,c+1). Pass 1: (r+1,c),(r+1,c+1).
    const float* __restrict__ base =
        x + ((size_t)((b * R_ + 2 * q) * C_ + 2 * p)) * D_;

    const uint4* __restrict__ sW4 = reinterpret_cast<const uint4*>(sW);

    unsigned long long nx[16], ny[16];             // 64 fp32 out accumulators
    float den = 0.0f;

#pragma unroll
    for (int pass = 0; pass < 2; ++pass) {
        const ulonglong2* __restrict__ pA = reinterpret_cast<const ulonglong2*>(
            base + (size_t)pass * (C_ * D_));
        const ulonglong2* __restrict__ pB = pA + 16;   // +64 floats

        ulonglong2 vA[16], vB[16];
#pragma unroll
        for (int k = 0; k < 16; ++k) vA[k] = pA[k];
#pragma unroll
        for (int k = 0; k < 16; ++k) vB[k] = pB[k];

        float lsA = 0.0f, lsB = 0.0f;

        for (int j = 0; j < H_; ++j) {
            unsigned long long a0 = 0ULL, a1 = 0ULL, b0 = 0ULL, b1 = 0ULL;
#pragma unroll
            for (int c = 0; c < 8; ++c) {
                uint4 w = sW4[j * 8 + c];          // 8 bf16 weights, broadcast
                unsigned long long w0 = bf2f2(w.x);
                unsigned long long w1 = bf2f2(w.y);
                unsigned long long w2 = bf2f2(w.z);
                unsigned long long w3 = bf2f2(w.w);
                ffma2(a0, vA[2 * c].x,     w0);
                ffma2(a1, vA[2 * c].y,     w1);
                ffma2(a0, vA[2 * c + 1].x, w2);
                ffma2(a1, vA[2 * c + 1].y, w3);
                ffma2(b0, vB[2 * c].x,     w0);
                ffma2(b1, vB[2 * c].y,     w1);
                ffma2(b0, vB[2 * c + 1].x, w2);
                ffma2(b1, vB[2 * c + 1].y, w3);
            }
            float f0, f1, f2, f3;
            upk2(a0, f0, f1);
            upk2(a1, f2, f3);
            float tA = (f0 + f1) + (f2 + f3) + sB[j];
            lsA = fmaf(tanh_fast(tA), sR[j], lsA);

            upk2(b0, f0, f1);
            upk2(b1, f2, f3);
            float tB = (f0 + f1) + (f2 + f3) + sB[j];
            lsB = fmaf(tanh_fast(tB), sR[j], lsB);
        }

        // logit = sigmoid(ls + br); unnormalized softmax weight e = exp(logit),
        // logit in (0,1) so e in (1,e): no overflow.
        const float eA = __expf(1.0f / (1.0f + __expf(-(lsA + brv))));
        const float eB = __expf(1.0f / (1.0f + __expf(-(lsB + brv))));
        den += eA + eB;
        const unsigned long long eeA = pk2(eA, eA);
        const unsigned long long eeB = pk2(eB, eB);

        if (pass == 0) {
#pragma unroll
            for (int k = 0; k < 16; ++k) {
                unsigned long long tx = 0ULL, ty = 0ULL;
                ffma2(tx, vA[k].x, eeA); ffma2(tx, vB[k].x, eeB);
                ffma2(ty, vA[k].y, eeA); ffma2(ty, vB[k].y, eeB);
                nx[k] = tx; ny[k] = ty;
            }
        } else {
#pragma unroll
            for (int k = 0; k < 16; ++k) {
                ffma2(nx[k], vA[k].x, eeA); ffma2(nx[k], vB[k].x, eeB);
                ffma2(ny[k], vA[k].y, eeA); ffma2(ny[k], vB[k].y, eeB);
            }
        }
    }

    const float inv = 1.0f / den;
    float4* __restrict__ op = reinterpret_cast<float4*>(out + (size_t)gidx * D_);
#pragma unroll
    for (int k = 0; k < 16; ++k) {
        float a, bv, c, d;
        upk2(nx[k], a, bv);
        upk2(ny[k], c, d);
        op[k] = make_float4(a * inv, bv * inv, c * inv, d * inv);
    }
}

extern "C" void kernel_launch(void* const* d_in, const int* in_sizes, int n_in,
                              void* d_out, int out_size)
{
    const float* x  = (const float*)d_in[0];
    const float* We = (const float*)d_in[1];
    const float* be = (const float*)d_in[2];
    const float* Wr = (const float*)d_in[3];
    const float* br = (const float*)d_in[4];
    float* out = (float*)d_out;

    // 32*64*64 = 131072 windows; 256 threads/block -> 512 blocks
    softpool2d_kernel<<<512, 256>>>(x, We, be, Wr, br, out);
}

// round 7
// speedup vs baseline: 6.1214x; 3.4175x over previous
#include <cuda_runtime.h>
#include <cuda_bf16.h>
#include <cstdint>

// SoftPool_2d: x (32,128,128,64) f32, 2x2/stride-2 windows.
// Round 7: expand GEMM on tensor pipe via warp-level mma.sync m16n8k16 bf16
// (baseline sm_80 PTX -> compiles under compute_103; tcgen05 is blocked by the
// harness's non-'a' PTX target). Per warp: 16 positions (= 4 windows) x 128
// hidden. A built in registers from global (f32->bf16), B = We^T bf16 in smem.
// Epilogue: tanh -> dot(Wr) -> sigmoid -> softmax over the 4 positions (quad +
// xor-16 shuffles) -> weighted sum of f32 x (L1-hot reload).

#define THREADS 256

__device__ __forceinline__ float tanh_fast(float x) {
    float y; asm("tanh.approx.f32 %0, %1;" : "=f"(y) : "f"(x)); return y;
}
__device__ __forceinline__ uint32_t pkbf2(float lo, float hi) {
    __nv_bfloat162 h = __floats2bfloat162_rn(lo, hi);
    return *reinterpret_cast<uint32_t*>(&h);
}
__device__ __forceinline__ void mma16816(float* c, const uint32_t* a,
                                         uint32_t b0, uint32_t b1) {
    asm volatile(
        "mma.sync.aligned.m16n8k16.row.col.f32.bf16.bf16.f32 "
        "{%0,%1,%2,%3}, {%4,%5,%6,%7}, {%8,%9}, {%0,%1,%2,%3};"
        : "+f"(c[0]), "+f"(c[1]), "+f"(c[2]), "+f"(c[3])
        : "r"(a[0]), "r"(a[1]), "r"(a[2]), "r"(a[3]), "r"(b0), "r"(b1));
}

// B rows padded to 72 bf16 (144B): within one LDS, bank = g*16 + quad*4 -> all
// 32 lanes hit distinct banks (conflict-free).
#define BSTRIDE 72

__global__ __launch_bounds__(THREADS, 2)
void softpool2d_mma_kernel(const float* __restrict__ x,
                           const float* __restrict__ We,
                           const float* __restrict__ be,
                           const float* __restrict__ Wr,
                           const float* __restrict__ br,
                           float* __restrict__ out)
{
    __shared__ __align__(16) __nv_bfloat16 sWt[128 * BSTRIDE];  // We^T, bf16
    __shared__ float sBias[128];
    __shared__ float sWr[128];

    const int tid = threadIdx.x;

    // Stage We^T: sWt[j][d] = bf16(We[d*128 + j])
    for (int idx = tid; idx < 64 * 128; idx += THREADS) {
        int d = idx >> 7;
        int j = idx & 127;
        sWt[j * BSTRIDE + d] = __float2bfloat16(We[idx]);
    }
    if (tid < 128) {
        sBias[tid] = be[tid];
        sWr[tid]   = Wr[tid];
    }
    __syncthreads();

    const float brv = br[0];

    // CTA -> 32 windows (half of one q-row): b = cta>>7; q = (cta&127)>>1;
    // p0 = (cta&1)*32. Warp handles 4 consecutive p.
    const int cta = blockIdx.x;
    const int b   = cta >> 7;
    const int rem = cta & 127;
    const int q   = rem >> 1;
    const int p0  = (rem & 1) * 32;

    const int wid  = tid >> 5;
    const int lane = tid & 31;
    const int g    = lane >> 2;       // octet group 0..7
    const int tq   = lane & 3;        // quad index

    // Warp-tile row mapping: row = i*4 + w  (i = position in 2x2, w = window).
    // Lane group g owns rows g (i = g>>2, dr=0) and g+8 (i = (g>>2)+2, dr=1).
    const int w  = g & 3;             // window within warp
    const int p  = p0 + wid * 4 + w;
    const int dc = g >> 2;            // column offset within window

    const int row0 = b * 128 + 2 * q;
    const float* __restrict__ xlo = x + ((size_t)row0 * 128 + 2 * p + dc) * 64;
    const float* __restrict__ xhi = xlo + 128 * 64;   // dr=1 row

    float acc[16][4];
#pragma unroll
    for (int n = 0; n < 16; ++n)
#pragma unroll
        for (int k = 0; k < 4; ++k) acc[n][k] = 0.0f;

#pragma unroll
    for (int kk = 0; kk < 4; ++kk) {
        const int ch = kk * 16 + tq * 2;
        uint32_t a[4];
        float2 f;
        f = *reinterpret_cast<const float2*>(xlo + ch);     a[0] = pkbf2(f.x, f.y);
        f = *reinterpret_cast<const float2*>(xhi + ch);     a[1] = pkbf2(f.x, f.y);
        f = *reinterpret_cast<const float2*>(xlo + ch + 8); a[2] = pkbf2(f.x, f.y);
        f = *reinterpret_cast<const float2*>(xhi + ch + 8); a[3] = pkbf2(f.x, f.y);

#pragma unroll
        for (int n = 0; n < 16; ++n) {
            const __nv_bfloat16* bp = &sWt[(n * 8 + g) * BSTRIDE + kk * 16 + tq * 2];
            uint32_t b0 = *reinterpret_cast<const uint32_t*>(bp);
            uint32_t b1 = *reinterpret_cast<const uint32_t*>(bp + 8);
            mma16816(acc[n], a, b0, b1);
        }
    }

    // Epilogue: lsA = row g (i = g>>2), lsB = row g+8 (i = (g>>2)+2).
    // C fragment: lane owns cols j = n*8 + tq*2 + {0,1}.
    float lsA = 0.0f, lsB = 0.0f;
#pragma unroll
    for (int n = 0; n < 16; ++n) {
        const int j = n * 8 + tq * 2;
        float2 bia = *reinterpret_cast<const float2*>(&sBias[j]);
        float2 wr2 = *reinterpret_cast<const float2*>(&sWr[j]);
        lsA = fmaf(tanh_fast(acc[n][0] + bia.x), wr2.x, lsA);
        lsA = fmaf(tanh_fast(acc[n][1] + bia.y), wr2.y, lsA);
        lsB = fmaf(tanh_fast(acc[n][2] + bia.x), wr2.x, lsB);
        lsB = fmaf(tanh_fast(acc[n][3] + bia.y), wr2.y, lsB);
    }
    // Reduce the 128-col dot across the quad
    lsA += __shfl_xor_sync(0xFFFFFFFFu, lsA, 1);
    lsA += __shfl_xor_sync(0xFFFFFFFFu, lsA, 2);
    lsB += __shfl_xor_sync(0xFFFFFFFFu, lsB, 1);
    lsB += __shfl_xor_sync(0xFFFFFFFFu, lsB, 2);

    // logit in (0,1); unnormalized softmax weight e = exp(logit) in (1,e)
    const float eA = __expf(1.0f / (1.0f + __expf(-(lsA + brv))));
    const float eB = __expf(1.0f / (1.0f + __expf(-(lsB + brv))));
    // Partner group g^4 holds the other two positions of this window
    const float pA = __shfl_xor_sync(0xFFFFFFFFu, eA, 16);
    const float pB = __shfl_xor_sync(0xFFFFFFFFu, eB, 16);

    float e0, e1, e2, e3;
    if (g < 4) { e0 = eA; e2 = eB; e1 = pA; e3 = pB; }
    else       { e1 = eA; e3 = eB; e0 = pA; e2 = pB; }
    const float inv = 1.0f / (e0 + e1 + e2 + e3);
    const float g0 = e0 * inv, g1 = e1 * inv, g2 = e2 * inv, g3 = e3 * inv;

    // Weighted sum in f32 (x reload is L1-hot). 8 lanes per window, 8 ch each.
    const int sub = ((g >> 2) << 2) + tq;   // 0..7 within window
    const int cb  = sub * 8;
    const float* __restrict__ x0 = x + ((size_t)row0 * 128 + 2 * p) * 64 + cb;
    const float* __restrict__ x1 = x0 + 64;          // dc=1
    const float* __restrict__ x2 = x0 + 128 * 64;    // dr=1
    const float* __restrict__ x3 = x2 + 64;
    float* __restrict__ dst = out + ((size_t)(b * 64 + q) * 64 + p) * 64 + cb;

#pragma unroll
    for (int c = 0; c < 2; ++c) {
        float4 a4 = reinterpret_cast<const float4*>(x0)[c];
        float4 b4 = reinterpret_cast<const float4*>(x1)[c];
        float4 c4 = reinterpret_cast<const float4*>(x2)[c];
        float4 d4 = reinterpret_cast<const float4*>(x3)[c];
        float4 o;
        o.x = g0 * a4.x + g1 * b4.x + g2 * c4.x + g3 * d4.x;
        o.y = g0 * a4.y + g1 * b4.y + g2 * c4.y + g3 * d4.y;
        o.z = g0 * a4.z + g1 * b4.z + g2 * c4.z + g3 * d4.z;
        o.w = g0 * a4.w + g1 * b4.w + g2 * c4.w + g3 * d4.w;
        reinterpret_cast<float4*>(dst)[c] = o;
    }
}

extern "C" void kernel_launch(void* const* d_in, const int* in_sizes, int n_in,
                              void* d_out, int out_size)
{
    const float* x  = (const float*)d_in[0];
    const float* We = (const float*)d_in[1];
    const float* be = (const float*)d_in[2];
    const float* Wr = (const float*)d_in[3];
    const float* br = (const float*)d_in[4];
    float* out = (float*)d_out;

    // 131072 windows / 32 per CTA = 4096 CTAs
    softpool2d_mma_kernel<<<4096, THREADS>>>(x, We, be, Wr, br, out);
}

// round 8
// speedup vs baseline: 7.0198x; 1.1468x over previous
#include <cuda_runtime.h>
#include <cuda_bf16.h>
#include <cstdint>

// SoftPool_2d: x (32,128,128,64) f32, 2x2/stride-2 windows.
// Round 8: same mma.sync m16n8k16 bf16 GEMM as round 7, but L1-wavefront
// optimized: A staged coalesced through SW128 smem + ldmatrix.x4; B read via
// ldmatrix.x4 from SW128 rows; epilogue lanes read contiguous 16B chunks.

#define THREADS 256

__device__ __forceinline__ float tanh_fast(float x) {
    float y; asm("tanh.approx.f32 %0, %1;" : "=f"(y) : "f"(x)); return y;
}
__device__ __forceinline__ uint32_t pkbf2(float lo, float hi) {
    __nv_bfloat162 h = __floats2bfloat162_rn(lo, hi);
    return *reinterpret_cast<uint32_t*>(&h);
}
__device__ __forceinline__ void mma16816(float* c, const uint32_t* a,
                                         uint32_t b0, uint32_t b1) {
    asm volatile(
        "mma.sync.aligned.m16n8k16.row.col.f32.bf16.bf16.f32 "
        "{%0,%1,%2,%3}, {%4,%5,%6,%7}, {%8,%9}, {%0,%1,%2,%3};"
        : "+f"(c[0]), "+f"(c[1]), "+f"(c[2]), "+f"(c[3])
        : "r"(a[0]), "r"(a[1]), "r"(a[2]), "r"(a[3]), "r"(b0), "r"(b1));
}
__device__ __forceinline__ void ldsm_x4(uint32_t* r, uint32_t addr) {
    asm volatile("ldmatrix.sync.aligned.m8n8.x4.shared.b16 {%0,%1,%2,%3}, [%4];"
                 : "=r"(r[0]), "=r"(r[1]), "=r"(r[2]), "=r"(r[3]) : "r"(addr));
}
__device__ __forceinline__ uint32_t swz(uint32_t off) {
    return off ^ ((off >> 3) & 0x70);      // SW128: 8 rows -> 8 distinct 16B slots
}

__global__ __launch_bounds__(THREADS, 2)
void softpool2d_mma_kernel(const float* __restrict__ x,
                           const float* __restrict__ We,
                           const float* __restrict__ be,
                           const float* __restrict__ Wr,
                           const float* __restrict__ br,
                           float* __restrict__ out)
{
    // B = We^T bf16: 128 rows (hidden j) x 64 ch = 128B rows, SW128. 16KB.
    __shared__ __align__(16) __nv_bfloat16 sB[128 * 64];
    // Per-warp A tiles: 16 rows (positions) x 64 ch bf16 = 2KB each. 16KB.
    __shared__ __align__(16) __nv_bfloat16 sA[8][16 * 64];
    __shared__ float sBias[128];
    __shared__ float sWr[128];

    const int tid = threadIdx.x;
    const int wid  = tid >> 5;
    const int lane = tid & 31;
    const int g    = lane >> 2;       // 0..7
    const int tq   = lane & 3;

    // Stage We^T (SW128-swizzled): row j holds We[:,j]
    {
        uint8_t* bp = reinterpret_cast<uint8_t*>(sB);
        for (int idx = tid; idx < 64 * 128; idx += THREADS) {
            int d = idx >> 7;
            int j = idx & 127;
            *reinterpret_cast<__nv_bfloat16*>(bp + swz((uint32_t)(j * 128 + d * 2)))
                = __float2bfloat16(We[idx]);
        }
    }
    if (tid < 128) {
        sBias[tid] = be[tid];
        sWr[tid]   = Wr[tid];
    }

    const float brv = br[0];

    // CTA -> 32 windows: b = cta>>7; q = (cta&127)>>1; p0 = (cta&1)*32.
    const int cta = blockIdx.x;
    const int b   = cta >> 7;
    const int rem = cta & 127;
    const int q   = rem >> 1;
    const int p0  = (rem & 1) * 32;
    const int pw  = p0 + wid * 4;     // warp's first window column
    const int row0 = b * 128 + 2 * q;

    const float* __restrict__ baseq = x + ((size_t)row0 * 128 + 2 * pw) * 64;
    const uint32_t aW = (uint32_t)__cvta_generic_to_shared(sA[wid]);
    const uint32_t bW = (uint32_t)__cvta_generic_to_shared(sB);

    // Stage A tile coalesced: row m = i*4 + w (i = pos in 2x2, w = window).
    // 256 float4 chunks; lanes 0-15 row 2t, 16-31 row 2t+1 (contiguous 256B).
#pragma unroll
    for (int it = 0; it < 8; ++it) {
        int ci = it * 32 + lane;          // 0..255
        int m  = ci >> 4;
        int c4 = ci & 15;
        int i  = m >> 2, w = m & 3;
        const float4 v = *reinterpret_cast<const float4*>(
            baseq + (i >> 1) * 8192 + w * 128 + (i & 1) * 64 + c4 * 4);
        uint32_t lo = pkbf2(v.x, v.y);
        uint32_t hi = pkbf2(v.z, v.w);
        uint32_t off = swz((uint32_t)(m * 128 + c4 * 8));
        asm volatile("st.shared.v2.b32 [%0], {%1,%2};"
                     :: "r"(aW + off), "r"(lo), "r"(hi) : "memory");
    }
    __syncthreads();

    // A fragments via ldmatrix.x4 (one per kk): rows = lane&15, khalf = lane>>4
    uint32_t af[4][4];
    {
        uint32_t rowb = (uint32_t)((lane & 15) * 128 + (lane >> 4) * 16);
#pragma unroll
        for (int kk = 0; kk < 4; ++kk)
            ldsm_x4(af[kk], aW + swz(rowb + kk * 32));
    }

    float acc[16][4];
#pragma unroll
    for (int n = 0; n < 16; ++n)
#pragma unroll
        for (int k = 0; k < 4; ++k) acc[n][k] = 0.0f;

    // B fragments via ldmatrix.x4: quad -> (n-subtile, k-half)
    const int quad = lane >> 3;
    const uint32_t brow = (uint32_t)(((quad >> 1) * 8 + (lane & 7)) * 128
                                     + (quad & 1) * 16);
#pragma unroll
    for (int kk = 0; kk < 4; ++kk) {
#pragma unroll
        for (int ntp = 0; ntp < 8; ++ntp) {
            uint32_t brr[4];
            ldsm_x4(brr, bW + swz((uint32_t)(ntp * 2048) + brow + kk * 32));
            mma16816(acc[2 * ntp],     af[kk], brr[0], brr[1]);
            mma16816(acc[2 * ntp + 1], af[kk], brr[2], brr[3]);
        }
    }

    // Epilogue: lsA = row g (pos i = g>>2), lsB = row g+8 (pos i = (g>>2)+2).
    float lsA = 0.0f, lsB = 0.0f;
#pragma unroll
    for (int n = 0; n < 16; ++n) {
        const int j = n * 8 + tq * 2;
        float2 bia = *reinterpret_cast<const float2*>(&sBias[j]);
        float2 wr2 = *reinterpret_cast<const float2*>(&sWr[j]);
        lsA = fmaf(tanh_fast(acc[n][0] + bia.x), wr2.x, lsA);
        lsA = fmaf(tanh_fast(acc[n][1] + bia.y), wr2.y, lsA);
        lsB = fmaf(tanh_fast(acc[n][2] + bia.x), wr2.x, lsB);
        lsB = fmaf(tanh_fast(acc[n][3] + bia.y), wr2.y, lsB);
    }
    lsA += __shfl_xor_sync(0xFFFFFFFFu, lsA, 1);
    lsA += __shfl_xor_sync(0xFFFFFFFFu, lsA, 2);
    lsB += __shfl_xor_sync(0xFFFFFFFFu, lsB, 1);
    lsB += __shfl_xor_sync(0xFFFFFFFFu, lsB, 2);

    // logit in (0,1); unnormalized softmax weight e = exp(logit) in (1,e)
    const float eA = __expf(1.0f / (1.0f + __expf(-(lsA + brv))));
    const float eB = __expf(1.0f / (1.0f + __expf(-(lsB + brv))));
    const float pA = __shfl_xor_sync(0xFFFFFFFFu, eA, 16);
    const float pB = __shfl_xor_sync(0xFFFFFFFFu, eB, 16);

    float e0, e1, e2, e3;
    if (g < 4) { e0 = eA; e2 = eB; e1 = pA; e3 = pB; }
    else       { e1 = eA; e3 = eB; e0 = pA; e2 = pB; }
    const float inv = 1.0f / (e0 + e1 + e2 + e3);
    const float g0 = e0 * inv, g1 = e1 * inv, g2 = e2 * inv, g3 = e3 * inv;

    // Weighted sum, f32 (L1-hot). Window w handled by its 8 lanes; each lane
    // owns 2 contiguous 16B chunks -> fully coalesced per window.
    const int w   = g & 3;
    const int sub = ((g >> 2) << 2) + tq;     // 0..7
    const int p   = pw + w;
    const float* __restrict__ wb = x + ((size_t)row0 * 128 + 2 * p) * 64;
    float* __restrict__ dst = out + ((size_t)(b * 64 + q) * 64 + p) * 64;

#pragma unroll
    for (int h = 0; h < 2; ++h) {
        const int off = h * 32 + sub * 4;
        float4 a4 = *reinterpret_cast<const float4*>(wb + off);
        float4 b4 = *reinterpret_cast<const float4*>(wb + 64 + off);
        float4 c4 = *reinterpret_cast<const float4*>(wb + 8192 + off);
        float4 d4 = *reinterpret_cast<const float4*>(wb + 8192 + 64 + off);
        float4 o;
        o.x = g0 * a4.x + g1 * b4.x + g2 * c4.x + g3 * d4.x;
        o.y = g0 * a4.y + g1 * b4.y + g2 * c4.y + g3 * d4.y;
        o.z = g0 * a4.z + g1 * b4.z + g2 * c4.z + g3 * d4.z;
        o.w = g0 * a4.w + g1 * b4.w + g2 * c4.w + g3 * d4.w;
        *reinterpret_cast<float4*>(dst + off) = o;
    }
}

extern "C" void kernel_launch(void* const* d_in, const int* in_sizes, int n_in,
                              void* d_out, int out_size)
{
    const float* x  = (const float*)d_in[0];
    const float* We = (const float*)d_in[1];
    const float* be = (const float*)d_in[2];
    const float* Wr = (const float*)d_in[3];
    const float* br = (const float*)d_in[4];
    float* out = (float*)d_out;

    // 131072 windows / 32 per CTA = 4096 CTAs
    softpool2d_mma_kernel<<<4096, THREADS>>>(x, We, be, Wr, br, out);
}

// round 9
// speedup vs baseline: 9.1410x; 1.3022x over previous
#include <cuda_runtime.h>
#include <cuda_bf16.h>
#include <cstdint>

// SoftPool_2d: x (32,128,128,64) f32, 2x2/stride-2 windows.
// Round 9: warp-M=32 (two 16-row A tiles share each B ldmatrix fragment ->
// B smem traffic per position halved), N processed in halves to cap acc regs,
// A fragments re-ldmatrix'd per (half,kk) so they stay transient, per-warp
// staging buffers -> no CTA-wide barriers in the main loop.

#define THREADS 256

// dynamic smem layout (bytes)
#define OFF_B    0          // We^T bf16, 128 rows x 128B, SW128   (16384)
#define OFF_A    16384      // per-warp A: 2 tiles x 16 rows x 128B (8*4096)
#define OFF_BIAS 49152      // 128 f32
#define OFF_WR   49664      // 128 f32
#define SMEM_SZ  50176

__device__ __forceinline__ float tanh_fast(float x) {
    float y; asm("tanh.approx.f32 %0, %1;" : "=f"(y) : "f"(x)); return y;
}
__device__ __forceinline__ uint32_t pkbf2(float lo, float hi) {
    __nv_bfloat162 h = __floats2bfloat162_rn(lo, hi);
    return *reinterpret_cast<uint32_t*>(&h);
}
__device__ __forceinline__ void mma16816(float* c, const uint32_t* a,
                                         uint32_t b0, uint32_t b1) {
    asm volatile(
        "mma.sync.aligned.m16n8k16.row.col.f32.bf16.bf16.f32 "
        "{%0,%1,%2,%3}, {%4,%5,%6,%7}, {%8,%9}, {%0,%1,%2,%3};"
        : "+f"(c[0]), "+f"(c[1]), "+f"(c[2]), "+f"(c[3])
        : "r"(a[0]), "r"(a[1]), "r"(a[2]), "r"(a[3]), "r"(b0), "r"(b1));
}
__device__ __forceinline__ void ldsm_x4(uint32_t* r, uint32_t addr) {
    asm volatile("ldmatrix.sync.aligned.m8n8.x4.shared.b16 {%0,%1,%2,%3}, [%4];"
                 : "=r"(r[0]), "=r"(r[1]), "=r"(r[2]), "=r"(r[3]) : "r"(addr));
}
__device__ __forceinline__ uint32_t swz(uint32_t off) {
    return off ^ ((off >> 3) & 0x70);
}

__global__ __launch_bounds__(THREADS, 2)
void softpool2d_mma_kernel(const float* __restrict__ x,
                           const float* __restrict__ We,
                           const float* __restrict__ be,
                           const float* __restrict__ Wr,
                           const float* __restrict__ br,
                           float* __restrict__ out)
{
    extern __shared__ __align__(16) unsigned char sm[];
    __nv_bfloat16* sB = reinterpret_cast<__nv_bfloat16*>(sm + OFF_B);
    float* sBias = reinterpret_cast<float*>(sm + OFF_BIAS);
    float* sWr   = reinterpret_cast<float*>(sm + OFF_WR);

    const int tid  = threadIdx.x;
    const int wid  = tid >> 5;
    const int lane = tid & 31;
    const int g    = lane >> 2;       // 0..7
    const int tq   = lane & 3;

    // Stage We^T (SW128-swizzled): row j holds We[:,j]
    {
        uint8_t* bp = reinterpret_cast<uint8_t*>(sB);
        for (int idx = tid; idx < 64 * 128; idx += THREADS) {
            int d = idx >> 7;
            int j = idx & 127;
            *reinterpret_cast<__nv_bfloat16*>(bp + swz((uint32_t)(j * 128 + d * 2)))
                = __float2bfloat16(We[idx]);
        }
    }
    if (tid < 128) {
        sBias[tid] = be[tid];
        sWr[tid]   = Wr[tid];
    }
    __syncthreads();          // the only CTA-wide barrier

    const float brv = br[0];

    // CTA = one full q-row of one batch: 64 windows. b = cta>>6, q = cta&63.
    const int cta = blockIdx.x;
    const int b   = cta >> 6;
    const int q   = cta & 63;
    const int row0 = b * 128 + 2 * q;
    const int pw  = wid * 8;          // warp covers windows p = pw..pw+7

    const float* __restrict__ baseq = x + ((size_t)row0 * 128 + 2 * pw) * 64;
    const uint32_t aW = (uint32_t)__cvta_generic_to_shared(sm + OFF_A) + wid * 4096;
    const uint32_t bW = (uint32_t)__cvta_generic_to_shared(sB);

    // Stage both A tiles (t=0: windows 0..3, t=1: windows 4..7).
    // Row m = i*4 + w (i = pos in 2x2, w = window). Per-warp buffer only.
#pragma unroll
    for (int t = 0; t < 2; ++t) {
        const float* __restrict__ bt = baseq + t * 512;
#pragma unroll
        for (int it = 0; it < 8; ++it) {
            int ci = it * 32 + lane;      // 0..255
            int m  = ci >> 4;
            int c4 = ci & 15;
            int i  = m >> 2, w = m & 3;
            const float4 v = *reinterpret_cast<const float4*>(
                bt + (i >> 1) * 8192 + w * 128 + (i & 1) * 64 + c4 * 4);
            uint32_t lo = pkbf2(v.x, v.y);
            uint32_t hi = pkbf2(v.z, v.w);
            uint32_t off = swz((uint32_t)(m * 128 + c4 * 8));
            asm volatile("st.shared.v2.b32 [%0], {%1,%2};"
                         :: "r"(aW + t * 2048 + off), "r"(lo), "r"(hi) : "memory");
        }
    }
    __syncwarp();

    const uint32_t arow = (uint32_t)((lane & 15) * 128 + (lane >> 4) * 16);
    const int quad = lane >> 3;
    const uint32_t brow = (uint32_t)(((quad >> 1) * 8 + (lane & 7)) * 128
                                     + (quad & 1) * 16);

    float lsA[2] = {0.0f, 0.0f}, lsB[2] = {0.0f, 0.0f};

#pragma unroll
    for (int h = 0; h < 2; ++h) {
        float acc[2][8][4];
#pragma unroll
        for (int t = 0; t < 2; ++t)
#pragma unroll
            for (int n = 0; n < 8; ++n)
#pragma unroll
                for (int k = 0; k < 4; ++k) acc[t][n][k] = 0.0f;

#pragma unroll
        for (int kk = 0; kk < 4; ++kk) {
            uint32_t af0[4], af1[4];
            ldsm_x4(af0, aW + swz(arow + kk * 32));
            ldsm_x4(af1, aW + 2048 + swz(arow + kk * 32));
#pragma unroll
            for (int ntp = 0; ntp < 4; ++ntp) {
                uint32_t brr[4];
                ldsm_x4(brr, bW + swz((uint32_t)((h * 4 + ntp) * 2048)
                                      + brow + kk * 32));
                mma16816(acc[0][2 * ntp],     af0, brr[0], brr[1]);
                mma16816(acc[0][2 * ntp + 1], af0, brr[2], brr[3]);
                mma16816(acc[1][2 * ntp],     af1, brr[0], brr[1]);
                mma16816(acc[1][2 * ntp + 1], af1, brr[2], brr[3]);
            }
        }

        // Partial epilogue for this N-half: tanh -> dot(Wr)
#pragma unroll
        for (int t = 0; t < 2; ++t) {
#pragma unroll
            for (int n = 0; n < 8; ++n) {
                const int j = h * 64 + n * 8 + tq * 2;
                float2 bia = *reinterpret_cast<const float2*>(&sBias[j]);
                float2 wr2 = *reinterpret_cast<const float2*>(&sWr[j]);
                lsA[t] = fmaf(tanh_fast(acc[t][n][0] + bia.x), wr2.x, lsA[t]);
                lsA[t] = fmaf(tanh_fast(acc[t][n][1] + bia.y), wr2.y, lsA[t]);
                lsB[t] = fmaf(tanh_fast(acc[t][n][2] + bia.x), wr2.x, lsB[t]);
                lsB[t] = fmaf(tanh_fast(acc[t][n][3] + bia.y), wr2.y, lsB[t]);
            }
        }
    }

#pragma unroll
    for (int t = 0; t < 2; ++t) {
        float a = lsA[t], bb = lsB[t];
        a += __shfl_xor_sync(0xFFFFFFFFu, a, 1);
        a += __shfl_xor_sync(0xFFFFFFFFu, a, 2);
        bb += __shfl_xor_sync(0xFFFFFFFFu, bb, 1);
        bb += __shfl_xor_sync(0xFFFFFFFFu, bb, 2);

        // logit in (0,1); unnormalized softmax weight e = exp(logit) in (1,e)
        const float eA = __expf(1.0f / (1.0f + __expf(-(a + brv))));
        const float eB = __expf(1.0f / (1.0f + __expf(-(bb + brv))));
        const float pA = __shfl_xor_sync(0xFFFFFFFFu, eA, 16);
        const float pB = __shfl_xor_sync(0xFFFFFFFFu, eB, 16);

        float e0, e1, e2, e3;
        if (g < 4) { e0 = eA; e2 = eB; e1 = pA; e3 = pB; }
        else       { e1 = eA; e3 = eB; e0 = pA; e2 = pB; }
        const float inv = 1.0f / (e0 + e1 + e2 + e3);
        const float g0 = e0 * inv, g1 = e1 * inv, g2 = e2 * inv, g3 = e3 * inv;

        // Weighted sum, f32 (L1-hot reload). Window w by its 8 lanes.
        const int w   = g & 3;
        const int sub = ((g >> 2) << 2) + tq;     // 0..7
        const int p   = pw + t * 4 + w;
        const float* __restrict__ wb = x + ((size_t)row0 * 128 + 2 * p) * 64;
        float* __restrict__ dst = out + ((size_t)(b * 64 + q) * 64 + p) * 64;

#pragma unroll
        for (int hh = 0; hh < 2; ++hh) {
            const int off = hh * 32 + sub * 4;
            float4 a4 = *reinterpret_cast<const float4*>(wb + off);
            float4 b4 = *reinterpret_cast<const float4*>(wb + 64 + off);
            float4 c4 = *reinterpret_cast<const float4*>(wb + 8192 + off);
            float4 d4 = *reinterpret_cast<const float4*>(wb + 8192 + 64 + off);
            float4 o;
            o.x = g0 * a4.x + g1 * b4.x + g2 * c4.x + g3 * d4.x;
            o.y = g0 * a4.y + g1 * b4.y + g2 * c4.y + g3 * d4.y;
            o.z = g0 * a4.z + g1 * b4.z + g2 * c4.z + g3 * d4.z;
            o.w = g0 * a4.w + g1 * b4.w + g2 * c4.w + g3 * d4.w;
            *reinterpret_cast<float4*>(dst + off) = o;
        }
    }
}

extern "C" void kernel_launch(void* const* d_in, const int* in_sizes, int n_in,
                              void* d_out, int out_size)
{
    const float* x  = (const float*)d_in[0];
    const float* We = (const float*)d_in[1];
    const float* be = (const float*)d_in[2];
    const float* Wr = (const float*)d_in[3];
    const float* br = (const float*)d_in[4];
    float* out = (float*)d_out;

    cudaFuncSetAttribute(softpool2d_mma_kernel,
                         cudaFuncAttributeMaxDynamicSharedMemorySize, SMEM_SZ);
    // 131072 windows / 64 per CTA = 2048 CTAs
    softpool2d_mma_kernel<<<2048, THREADS, SMEM_SZ>>>(x, We, be, Wr, br, out);
}